// round 2
// baseline (speedup 1.0000x reference)
#include <cuda_runtime.h>
#include <cuda_bf16.h>

#define NODES 50000
#define EDGES 800000
#define NTYPE 3
#define CH    64

// ---------------- static device scratch (no allocation) ----------------
__device__ float d_A[NTYPE * NODES * CH];    // A[t][n][c] = feat[n] @ W1[t][0:64,:]
__device__ float d_B[NTYPE * NODES * CH];    // B[t][n][c] = feat[n] @ W1[t][64:128,:]
__device__ float d_S[NTYPE * NODES * CH];    // raw p scatter sums per (t,dst,c)
__device__ int   d_cnt[NTYPE * NODES];       // edge counts per (t,dst)
__device__ float d_sumP[NTYPE * CH];         // BN: sum p
__device__ float d_sumQ[NTYPE * CH];         // BN: sum p^2
__device__ float d_scale[NTYPE * CH];        // BN affine (derived)
__device__ float d_shift[NTYPE * CH];
__device__ int   d_src[NTYPE * EDGES];
__device__ int   d_dst[NTYPE * EDGES];
__device__ int   d_is64;

// ---------------- helpers ----------------
static __device__ __forceinline__ unsigned long long pack2(float x, float y) {
    unsigned long long r;
    asm("mov.b64 %0, {%1,%2};" : "=l"(r) : "f"(x), "f"(y));
    return r;
}
static __device__ __forceinline__ float2 unpack2(unsigned long long v) {
    float2 f;
    asm("mov.b64 {%0,%1}, %2;" : "=f"(f.x), "=f"(f.y) : "l"(v));
    return f;
}
static __device__ __forceinline__ void ffma2(unsigned long long& d,
                                             unsigned long long a,
                                             unsigned long long b) {
    asm("fma.rn.f32x2 %0, %1, %2, %0;" : "+l"(d) : "l"(a), "l"(b));
}
static __device__ __forceinline__ void red2(float* addr, float x, float y) {
    asm volatile("red.global.add.v2.f32 [%0], {%1, %2};"
                 :: "l"(addr), "f"(x), "f"(y) : "memory");
}
static __device__ __forceinline__ float elu1(float x) {
    return x > 0.f ? x : (__expf(x) - 1.f);
}

// ---------------- K0: detect int64 vs int32 edge indices ----------------
__global__ void k_detect(const int* __restrict__ raw) {
    if (threadIdx.x == 0) {
        int is64 = 1;
        for (int i = 0; i < 64; i++) {
            if (raw[2 * i + 1] != 0) { is64 = 0; break; }
        }
        d_is64 = is64;
    }
}

// ---------------- K1: normalize edge indices to int32 ----------------
__global__ void k_convert(const void* __restrict__ sraw, const void* __restrict__ draw) {
    long long i = (long long)blockIdx.x * blockDim.x + threadIdx.x;
    if (i >= (long long)NTYPE * EDGES) return;
    if (d_is64) {
        d_src[i] = (int)((const long long*)sraw)[i];
        d_dst[i] = (int)((const long long*)draw)[i];
    } else {
        d_src[i] = ((const int*)sraw)[i];
        d_dst[i] = ((const int*)draw)[i];
    }
}

// ---------------- K1b: zero scratch ----------------
__global__ void k_zero() {
    long long i = (long long)blockIdx.x * blockDim.x + threadIdx.x;
    const long long nS4 = (long long)NTYPE * NODES * CH / 4;   // float4 count
    if (i < nS4) {
        ((float4*)d_S)[i] = make_float4(0.f, 0.f, 0.f, 0.f);
    }
    if (i < NTYPE * NODES) d_cnt[i] = 0;
    if (i < NTYPE * CH) { d_sumP[i] = 0.f; d_sumQ[i] = 0.f; }
}

// ---------------- K2: precompute A/B = features @ W1 halves ----------------
__global__ void __launch_bounds__(128) k_pre(const float* __restrict__ feats,
                                             const float* __restrict__ W1) {
    __shared__ float w1t[128 * 64];  // w1t[o*64+k]
    const int t = blockIdx.y;
    const float* W1t = W1 + t * 128 * 64;
    for (int i = threadIdx.x; i < 128 * 64; i += 128) {
        int o = i >> 6, k = i & 63;
        w1t[i] = W1t[(((o >> 6) << 6) + k) * 64 + (o & 63)];
    }
    __syncthreads();
    int n = blockIdx.x * 128 + threadIdx.x;
    if (n >= NODES) return;

    float f[64];
#pragma unroll
    for (int j = 0; j < 16; j++) {
        float4 v = *(const float4*)(feats + (size_t)n * 64 + 4 * j);
        f[4 * j] = v.x; f[4 * j + 1] = v.y; f[4 * j + 2] = v.z; f[4 * j + 3] = v.w;
    }
    float* outA = d_A + ((size_t)t * NODES + n) * 64;
    float* outB = d_B + ((size_t)t * NODES + n) * 64;

    for (int og = 0; og < 32; og++) {
        float a0 = 0.f, a1 = 0.f, a2 = 0.f, a3 = 0.f;
        const float* wp = &w1t[og * 4 * 64];
#pragma unroll
        for (int k = 0; k < 64; k += 4) {
            float4 v0 = *(const float4*)(wp + 0 * 64 + k);
            float4 v1 = *(const float4*)(wp + 1 * 64 + k);
            float4 v2 = *(const float4*)(wp + 2 * 64 + k);
            float4 v3 = *(const float4*)(wp + 3 * 64 + k);
            a0 = fmaf(v0.x, f[k], a0); a0 = fmaf(v0.y, f[k + 1], a0);
            a0 = fmaf(v0.z, f[k + 2], a0); a0 = fmaf(v0.w, f[k + 3], a0);
            a1 = fmaf(v1.x, f[k], a1); a1 = fmaf(v1.y, f[k + 1], a1);
            a1 = fmaf(v1.z, f[k + 2], a1); a1 = fmaf(v1.w, f[k + 3], a1);
            a2 = fmaf(v2.x, f[k], a2); a2 = fmaf(v2.y, f[k + 1], a2);
            a2 = fmaf(v2.z, f[k + 2], a2); a2 = fmaf(v2.w, f[k + 3], a2);
            a3 = fmaf(v3.x, f[k], a3); a3 = fmaf(v3.y, f[k + 1], a3);
            a3 = fmaf(v3.z, f[k + 2], a3); a3 = fmaf(v3.w, f[k + 3], a3);
        }
        float4 r = make_float4(a0, a1, a2, a3);
        if (og < 16) *(float4*)(outA + og * 4) = r;
        else         *(float4*)(outB + (og - 16) * 4) = r;
    }
}

// ---------------- K3: the edge kernel ----------------
__global__ void __launch_bounds__(128) k_edge(const float* __restrict__ W2,
                                              const float* __restrict__ b1,
                                              const float* __restrict__ lng,
                                              const float* __restrict__ lnb,
                                              const float* __restrict__ b2) {
    const int t = blockIdx.y;
    const int w = threadIdx.x >> 5;
    const int lane = threadIdx.x & 31;
    const int c0 = lane * 2;

    __shared__ __align__(16) float hdup[4][128];  // duplicated hn pairs per warp

    // register-cached W2 column pairs: w2r[k] = (W2[t][k][c0], W2[t][k][c0+1])
    unsigned long long w2r[64];
    const float* W2t = W2 + t * 64 * 64 + c0;
#pragma unroll
    for (int k = 0; k < 64; k++) {
        float2 wv = *(const float2*)(W2t + k * 64);
        w2r[k] = pack2(wv.x, wv.y);
    }
    const float2 b1v = *(const float2*)(b1 + t * 64 + c0);
    const float2 gv  = *(const float2*)(lng + t * 64 + c0);
    const float2 lbv = *(const float2*)(lnb + t * 64 + c0);
    const float2 b2v = *(const float2*)(b2 + t * 64 + c0);
    const unsigned long long accInit = pack2(b2v.x, b2v.y);

    const int*   srcp = d_src + (size_t)t * EDGES;
    const int*   dstp = d_dst + (size_t)t * EDGES;
    const float* At   = d_A + (size_t)t * NODES * 64;
    const float* Bt   = d_B + (size_t)t * NODES * 64;
    float*       St   = d_S + (size_t)t * NODES * 64;
    int*         cntp = d_cnt + (size_t)t * NODES;

    float sp0 = 0.f, sp1 = 0.f, sq0 = 0.f, sq1 = 0.f;

    const int stride = gridDim.x * 4;
    int e = blockIdx.x * 4 + w;

    if (e < EDGES) {
        int dst = dstp[e];
        int src = srcp[e];
        float2 av = *(const float2*)(At + (size_t)src * 64 + c0);
        float2 bv = *(const float2*)(Bt + (size_t)dst * 64 + c0);

        while (true) {
            const int e_next = e + stride;
            const bool more = (e_next < EDGES);

            // elu(A+B+b1) then LayerNorm over 64 channels (warp reduce)
            float h0 = elu1(av.x + bv.x + b1v.x);
            float h1 = elu1(av.y + bv.y + b1v.y);
            float s = h0 + h1;
            float q = fmaf(h0, h0, h1 * h1);
#pragma unroll
            for (int off = 16; off; off >>= 1) {
                s += __shfl_xor_sync(0xffffffffu, s, off);
                q += __shfl_xor_sync(0xffffffffu, q, off);
            }
            const float mu = s * (1.f / 64.f);
            const float var = fmaf(q, (1.f / 64.f), -mu * mu);
            const float rstd = rsqrtf(var + 1e-5f);
            const float hn0 = fmaf((h0 - mu) * rstd, gv.x, lbv.x);
            const float hn1 = fmaf((h1 - mu) * rstd, gv.y, lbv.y);
            *(float4*)(&hdup[w][4 * lane]) = make_float4(hn0, hn0, hn1, hn1);
            __syncwarp();

            // prefetch next edge's operands under the GEMM
            const int sdst = dst;
            float2 av_n = make_float2(0.f, 0.f), bv_n = make_float2(0.f, 0.f);
            int dst_n = 0;
            if (more) {
                int src_n = srcp[e_next];
                dst_n = dstp[e_next];
                av_n = *(const float2*)(At + (size_t)src_n * 64 + c0);
                bv_n = *(const float2*)(Bt + (size_t)dst_n * 64 + c0);
            }

            // GEMM2: p[c0..c0+1] = hn @ W2 + b2 (packed f32x2)
            unsigned long long acc = accInit;
            const ulonglong2* hp = (const ulonglong2*)&hdup[w][0];
#pragma unroll
            for (int kk = 0; kk < 32; kk++) {
                ulonglong2 hh = hp[kk];
                ffma2(acc, hh.x, w2r[2 * kk]);
                ffma2(acc, hh.y, w2r[2 * kk + 1]);
            }
            float2 pr = unpack2(acc);
            const float p0 = elu1(pr.x);
            const float p1 = elu1(pr.y);

            // BN running sums (register accumulation)
            sp0 += p0; sp1 += p1;
            sq0 = fmaf(p0, p0, sq0);
            sq1 = fmaf(p1, p1, sq1);

            // scatter raw p (vector reduction, no return)
            red2(St + (size_t)sdst * 64 + c0, p0, p1);
            if (lane == 0) atomicAdd(cntp + sdst, 1);

            __syncwarp();
            if (!more) break;
            e = e_next; dst = dst_n; av = av_n; bv = bv_n;
        }
    }
    // flush BN partial sums
    atomicAdd(d_sumP + t * 64 + c0,     sp0);
    atomicAdd(d_sumP + t * 64 + c0 + 1, sp1);
    atomicAdd(d_sumQ + t * 64 + c0,     sq0);
    atomicAdd(d_sumQ + t * 64 + c0 + 1, sq1);
}

// ---------------- K4: BN stats -> affine scale/shift ----------------
__global__ void k_stats(const float* __restrict__ bng, const float* __restrict__ bnb) {
    int i = threadIdx.x;
    if (i < NTYPE * CH) {
        const float invE = 1.f / (float)EDGES;
        float m = d_sumP[i] * invE;
        float v = fmaf(d_sumQ[i], invE, -m * m);
        float sc = bng[i] * rsqrtf(v + 1e-5f);
        d_scale[i] = sc;
        d_shift[i] = fmaf(-m, sc, bnb[i]);
    }
}

// ---------------- K5: node kernel: apply BN affine, GEMV Wr, residual ----------------
__global__ void __launch_bounds__(128) k_node(const float* __restrict__ feats,
                                              const float* __restrict__ Wr,
                                              const float* __restrict__ br,
                                              float* __restrict__ out) {
    __shared__ float wr[64 * 64];
    __shared__ float sc[NTYPE * CH], sh[NTYPE * CH];
    for (int i = threadIdx.x; i < 64 * 64; i += 128) wr[i] = Wr[i];
    for (int i = threadIdx.x; i < NTYPE * CH; i += 128) {
        sc[i] = d_scale[i];
        sh[i] = d_shift[i];
    }
    __syncthreads();

    int n = blockIdx.x * 128 + threadIdx.x;
    if (n >= NODES) return;

    // u[c] = sum_t scale*S + shift*cnt
    float u[64];
#pragma unroll
    for (int c = 0; c < 64; c++) u[c] = 0.f;
#pragma unroll
    for (int t = 0; t < NTYPE; t++) {
        const float cf = (float)d_cnt[t * NODES + n];
        const float* Sn = d_S + ((size_t)t * NODES + n) * 64;
#pragma unroll
        for (int j = 0; j < 16; j++) {
            float4 sv = *(const float4*)(Sn + 4 * j);
            u[4 * j + 0] = fmaf(sc[t * 64 + 4 * j + 0], sv.x, fmaf(sh[t * 64 + 4 * j + 0], cf, u[4 * j + 0]));
            u[4 * j + 1] = fmaf(sc[t * 64 + 4 * j + 1], sv.y, fmaf(sh[t * 64 + 4 * j + 1], cf, u[4 * j + 1]));
            u[4 * j + 2] = fmaf(sc[t * 64 + 4 * j + 2], sv.z, fmaf(sh[t * 64 + 4 * j + 2], cf, u[4 * j + 2]));
            u[4 * j + 3] = fmaf(sc[t * 64 + 4 * j + 3], sv.w, fmaf(sh[t * 64 + 4 * j + 3], cf, u[4 * j + 3]));
        }
    }

    // out = u @ Wr + br + feats
    const float* fn = feats + (size_t)n * 64;
    float* on = out + (size_t)n * 64;
    for (int o = 0; o < 64; o += 4) {
        float a0 = br[o], a1 = br[o + 1], a2 = br[o + 2], a3 = br[o + 3];
#pragma unroll
        for (int k = 0; k < 64; k++) {
            float4 wv = *(const float4*)(&wr[k * 64 + o]);
            a0 = fmaf(u[k], wv.x, a0);
            a1 = fmaf(u[k], wv.y, a1);
            a2 = fmaf(u[k], wv.z, a2);
            a3 = fmaf(u[k], wv.w, a3);
        }
        float4 fv = *(const float4*)(fn + o);
        float4 r = make_float4(a0 + fv.x, a1 + fv.y, a2 + fv.z, a3 + fv.w);
        *(float4*)(on + o) = r;
    }
}

// ---------------- launch ----------------
extern "C" void kernel_launch(void* const* d_in, const int* in_sizes, int n_in,
                              void* d_out, int out_size) {
    const float* feats = (const float*)d_in[0];
    const float* W1    = (const float*)d_in[1];
    const float* b1    = (const float*)d_in[2];
    const float* lng   = (const float*)d_in[3];
    const float* lnb   = (const float*)d_in[4];
    const float* W2    = (const float*)d_in[5];
    const float* b2    = (const float*)d_in[6];
    const float* bng   = (const float*)d_in[7];
    const float* bnb   = (const float*)d_in[8];
    const float* Wr    = (const float*)d_in[9];
    const float* br    = (const float*)d_in[10];
    const void*  esrc  = d_in[11];
    const void*  edst  = d_in[12];
    float* out = (float*)d_out;

    k_detect<<<1, 32>>>((const int*)esrc);

    {
        long long tot = (long long)NTYPE * EDGES;
        int blocks = (int)((tot + 255) / 256);
        k_convert<<<blocks, 256>>>(esrc, edst);
    }
    {
        long long nS4 = (long long)NTYPE * NODES * CH / 4;
        int blocks = (int)((nS4 + 255) / 256);
        k_zero<<<blocks, 256>>>();
    }
    {
        dim3 g((NODES + 127) / 128, NTYPE);
        k_pre<<<g, 128>>>(feats, W1);
    }
    {
        dim3 g(296, NTYPE);
        k_edge<<<g, 128>>>(W2, b1, lng, lnb, b2);
    }
    k_stats<<<1, 256>>>(bng, bnb);
    {
        int blocks = (NODES + 127) / 128;
        k_node<<<blocks, 128>>>(feats, Wr, br, out);
    }
}

// round 3
// speedup vs baseline: 1.5662x; 1.5662x over previous
#include <cuda_runtime.h>
#include <cuda_bf16.h>

#define NODES 50000
#define EDGES 800000
#define NTYPE 3
#define CH    64

// ---------------- static device scratch (no allocation) ----------------
__device__ float d_A[NTYPE * NODES * CH];    // A[t][n][c] = feat[n] @ W1[t][0:64,:]
__device__ float d_B[NTYPE * NODES * CH];    // B[t][n][c] = feat[n] @ W1[t][64:128,:]
__device__ float d_S[NTYPE * NODES * CH];    // raw p scatter sums per (t,dst,c)
__device__ int   d_cnt[NTYPE * NODES];       // edge counts per (t,dst)
__device__ float d_sumP[NTYPE * CH];         // BN: sum p
__device__ float d_sumQ[NTYPE * CH];         // BN: sum p^2
__device__ float d_scale[NTYPE * CH];        // BN affine (derived)
__device__ float d_shift[NTYPE * CH];
__device__ int   d_src[NTYPE * EDGES];
__device__ int   d_dst[NTYPE * EDGES];
__device__ int   d_is64;

// ---------------- helpers ----------------
static __device__ __forceinline__ unsigned long long pack2(float x, float y) {
    unsigned long long r;
    asm("mov.b64 %0, {%1,%2};" : "=l"(r) : "f"(x), "f"(y));
    return r;
}
static __device__ __forceinline__ float2 unpack2(unsigned long long v) {
    float2 f;
    asm("mov.b64 {%0,%1}, %2;" : "=f"(f.x), "=f"(f.y) : "l"(v));
    return f;
}
static __device__ __forceinline__ void ffma2(unsigned long long& d,
                                             unsigned long long a,
                                             unsigned long long b) {
    asm("fma.rn.f32x2 %0, %1, %2, %0;" : "+l"(d) : "l"(a), "l"(b));
}
static __device__ __forceinline__ void red2(float* addr, float x, float y) {
    asm volatile("red.global.add.v2.f32 [%0], {%1, %2};"
                 :: "l"(addr), "f"(x), "f"(y) : "memory");
}
static __device__ __forceinline__ float elu1(float x) {
    return x > 0.f ? x : (__expf(x) - 1.f);
}

// ---------------- K0: detect int64 vs int32 edge indices ----------------
__global__ void k_detect(const int* __restrict__ raw) {
    if (threadIdx.x == 0) {
        int is64 = 1;
        for (int i = 0; i < 64; i++) {
            if (raw[2 * i + 1] != 0) { is64 = 0; break; }
        }
        d_is64 = is64;
    }
}

// ---------------- K1: normalize edge indices to int32 ----------------
__global__ void k_convert(const void* __restrict__ sraw, const void* __restrict__ draw) {
    long long i = (long long)blockIdx.x * blockDim.x + threadIdx.x;
    if (i >= (long long)NTYPE * EDGES) return;
    if (d_is64) {
        d_src[i] = (int)((const long long*)sraw)[i];
        d_dst[i] = (int)((const long long*)draw)[i];
    } else {
        d_src[i] = ((const int*)sraw)[i];
        d_dst[i] = ((const int*)draw)[i];
    }
}

// ---------------- K1b: zero scratch ----------------
__global__ void k_zero() {
    long long i = (long long)blockIdx.x * blockDim.x + threadIdx.x;
    const long long nS4 = (long long)NTYPE * NODES * CH / 4;   // float4 count
    if (i < nS4) {
        ((float4*)d_S)[i] = make_float4(0.f, 0.f, 0.f, 0.f);
    }
    if (i < NTYPE * NODES) d_cnt[i] = 0;
    if (i < NTYPE * CH) { d_sumP[i] = 0.f; d_sumQ[i] = 0.f; }
}

// ---------------- K2: precompute A/B = features @ W1 halves ----------------
__global__ void __launch_bounds__(128) k_pre(const float* __restrict__ feats,
                                             const float* __restrict__ W1) {
    __shared__ float w1t[128 * 64];  // w1t[o*64+k]
    const int t = blockIdx.y;
    const float* W1t = W1 + t * 128 * 64;
    for (int i = threadIdx.x; i < 128 * 64; i += 128) {
        int o = i >> 6, k = i & 63;
        w1t[i] = W1t[(((o >> 6) << 6) + k) * 64 + (o & 63)];
    }
    __syncthreads();
    int n = blockIdx.x * 128 + threadIdx.x;
    if (n >= NODES) return;

    float f[64];
#pragma unroll
    for (int j = 0; j < 16; j++) {
        float4 v = *(const float4*)(feats + (size_t)n * 64 + 4 * j);
        f[4 * j] = v.x; f[4 * j + 1] = v.y; f[4 * j + 2] = v.z; f[4 * j + 3] = v.w;
    }
    float* outA = d_A + ((size_t)t * NODES + n) * 64;
    float* outB = d_B + ((size_t)t * NODES + n) * 64;

    for (int og = 0; og < 32; og++) {
        float a0 = 0.f, a1 = 0.f, a2 = 0.f, a3 = 0.f;
        const float* wp = &w1t[og * 4 * 64];
#pragma unroll
        for (int k = 0; k < 64; k += 4) {
            float4 v0 = *(const float4*)(wp + 0 * 64 + k);
            float4 v1 = *(const float4*)(wp + 1 * 64 + k);
            float4 v2 = *(const float4*)(wp + 2 * 64 + k);
            float4 v3 = *(const float4*)(wp + 3 * 64 + k);
            a0 = fmaf(v0.x, f[k], a0); a0 = fmaf(v0.y, f[k + 1], a0);
            a0 = fmaf(v0.z, f[k + 2], a0); a0 = fmaf(v0.w, f[k + 3], a0);
            a1 = fmaf(v1.x, f[k], a1); a1 = fmaf(v1.y, f[k + 1], a1);
            a1 = fmaf(v1.z, f[k + 2], a1); a1 = fmaf(v1.w, f[k + 3], a1);
            a2 = fmaf(v2.x, f[k], a2); a2 = fmaf(v2.y, f[k + 1], a2);
            a2 = fmaf(v2.z, f[k + 2], a2); a2 = fmaf(v2.w, f[k + 3], a2);
            a3 = fmaf(v3.x, f[k], a3); a3 = fmaf(v3.y, f[k + 1], a3);
            a3 = fmaf(v3.z, f[k + 2], a3); a3 = fmaf(v3.w, f[k + 3], a3);
        }
        float4 r = make_float4(a0, a1, a2, a3);
        if (og < 16) *(float4*)(outA + og * 4) = r;
        else         *(float4*)(outB + (og - 16) * 4) = r;
    }
}

// ---------------- K3: edge kernel, dual-edge pipelined ----------------
__global__ void __launch_bounds__(128, 3) k_edge(const float* __restrict__ W2,
                                                 const float* __restrict__ b1,
                                                 const float* __restrict__ lng,
                                                 const float* __restrict__ lnb,
                                                 const float* __restrict__ b2) {
    const int t = blockIdx.y;
    const int w = threadIdx.x >> 5;
    const int lane = threadIdx.x & 31;
    const int c0 = lane * 2;

    __shared__ __align__(16) float hdup[4][2][128];  // per warp, 2 edges of dup pairs

    // register-cached W2 column pairs
    unsigned long long w2r[64];
    const float* W2t = W2 + t * 64 * 64 + c0;
#pragma unroll
    for (int k = 0; k < 64; k++) {
        float2 wv = *(const float2*)(W2t + k * 64);
        w2r[k] = pack2(wv.x, wv.y);
    }
    const float2 b1v = *(const float2*)(b1 + t * 64 + c0);
    const float2 gv  = *(const float2*)(lng + t * 64 + c0);
    const float2 lbv = *(const float2*)(lnb + t * 64 + c0);
    const float2 b2v = *(const float2*)(b2 + t * 64 + c0);
    const unsigned long long accInit = pack2(b2v.x, b2v.y);

    const int*   srcp = d_src + (size_t)t * EDGES;
    const int*   dstp = d_dst + (size_t)t * EDGES;
    const float* At   = d_A + (size_t)t * NODES * 64;
    const float* Bt   = d_B + (size_t)t * NODES * 64;
    float*       St   = d_S + (size_t)t * NODES * 64;
    int*         cntp = d_cnt + (size_t)t * NODES;

    float sp0 = 0.f, sp1 = 0.f, sq0 = 0.f, sq1 = 0.f;

    const int npairs  = EDGES / 2;
    const int pstride = gridDim.x * 4;
    int pair = blockIdx.x * 4 + w;

    if (pair < npairs) {
        int e = pair * 2;
        int d0 = dstp[e],     s0 = srcp[e];
        int d1 = dstp[e + 1], s1 = srcp[e + 1];
        float2 av0 = *(const float2*)(At + (size_t)s0 * 64 + c0);
        float2 bv0 = *(const float2*)(Bt + (size_t)d0 * 64 + c0);
        float2 av1 = *(const float2*)(At + (size_t)s1 * 64 + c0);
        float2 bv1 = *(const float2*)(Bt + (size_t)d1 * 64 + c0);

        while (true) {
            const int pnext = pair + pstride;
            const bool more = (pnext < npairs);

            // --- LN for both edges (independent shuffle chains interleave) ---
            float h00 = elu1(av0.x + bv0.x + b1v.x);
            float h01 = elu1(av0.y + bv0.y + b1v.y);
            float h10 = elu1(av1.x + bv1.x + b1v.x);
            float h11 = elu1(av1.y + bv1.y + b1v.y);
            float sA = h00 + h01,               sB = h10 + h11;
            float qA = fmaf(h00, h00, h01 * h01), qB = fmaf(h10, h10, h11 * h11);
#pragma unroll
            for (int off = 16; off; off >>= 1) {
                sA += __shfl_xor_sync(0xffffffffu, sA, off);
                qA += __shfl_xor_sync(0xffffffffu, qA, off);
                sB += __shfl_xor_sync(0xffffffffu, sB, off);
                qB += __shfl_xor_sync(0xffffffffu, qB, off);
            }
            {
                const float muA = sA * (1.f / 64.f);
                const float rsA = rsqrtf(fmaf(qA, (1.f / 64.f), -muA * muA) + 1e-5f);
                const float muB = sB * (1.f / 64.f);
                const float rsB = rsqrtf(fmaf(qB, (1.f / 64.f), -muB * muB) + 1e-5f);
                float hn0 = fmaf((h00 - muA) * rsA, gv.x, lbv.x);
                float hn1 = fmaf((h01 - muA) * rsA, gv.y, lbv.y);
                *(float4*)(&hdup[w][0][4 * lane]) = make_float4(hn0, hn0, hn1, hn1);
                hn0 = fmaf((h10 - muB) * rsB, gv.x, lbv.x);
                hn1 = fmaf((h11 - muB) * rsB, gv.y, lbv.y);
                *(float4*)(&hdup[w][1][4 * lane]) = make_float4(hn0, hn0, hn1, hn1);
            }
            __syncwarp();

            // --- prefetch next pair under the GEMM ---
            const int wd0 = d0, wd1 = d1;
            int d0n = 0, d1n = 0;
            float2 av0n = make_float2(0.f, 0.f), bv0n = av0n;
            float2 av1n = av0n, bv1n = av0n;
            if (more) {
                const int en = pnext * 2;
                const int s0n = srcp[en];     d0n = dstp[en];
                const int s1n = srcp[en + 1]; d1n = dstp[en + 1];
                av0n = *(const float2*)(At + (size_t)s0n * 64 + c0);
                bv0n = *(const float2*)(Bt + (size_t)d0n * 64 + c0);
                av1n = *(const float2*)(At + (size_t)s1n * 64 + c0);
                bv1n = *(const float2*)(Bt + (size_t)d1n * 64 + c0);
            }

            // --- GEMM2 for both edges, split accumulators (4 chains) ---
            unsigned long long a0a = accInit, a0b = 0ULL;
            unsigned long long a1a = accInit, a1b = 0ULL;
            const ulonglong2* hp0 = (const ulonglong2*)&hdup[w][0][0];
            const ulonglong2* hp1 = (const ulonglong2*)&hdup[w][1][0];
#pragma unroll
            for (int kk = 0; kk < 32; kk++) {
                ulonglong2 h0 = hp0[kk];
                ulonglong2 h1 = hp1[kk];
                ffma2(a0a, h0.x, w2r[2 * kk]);
                ffma2(a0b, h0.y, w2r[2 * kk + 1]);
                ffma2(a1a, h1.x, w2r[2 * kk]);
                ffma2(a1b, h1.y, w2r[2 * kk + 1]);
            }
            float2 r0a = unpack2(a0a), r0b = unpack2(a0b);
            float2 r1a = unpack2(a1a), r1b = unpack2(a1b);
            const float p00 = elu1(r0a.x + r0b.x);
            const float p01 = elu1(r0a.y + r0b.y);
            const float p10 = elu1(r1a.x + r1b.x);
            const float p11 = elu1(r1a.y + r1b.y);

            // BN running sums
            sp0 += p00 + p10;
            sp1 += p01 + p11;
            sq0 += fmaf(p00, p00, p10 * p10);
            sq1 += fmaf(p01, p01, p11 * p11);

            // scatter raw p
            red2(St + (size_t)wd0 * 64 + c0, p00, p01);
            red2(St + (size_t)wd1 * 64 + c0, p10, p11);
            if (lane == 0)      atomicAdd(cntp + wd0, 1);
            else if (lane == 1) atomicAdd(cntp + wd1, 1);

            __syncwarp();
            if (!more) break;
            pair = pnext;
            d0 = d0n; d1 = d1n;
            av0 = av0n; bv0 = bv0n; av1 = av1n; bv1 = bv1n;
        }
    }
    // flush BN partial sums
    atomicAdd(d_sumP + t * 64 + c0,     sp0);
    atomicAdd(d_sumP + t * 64 + c0 + 1, sp1);
    atomicAdd(d_sumQ + t * 64 + c0,     sq0);
    atomicAdd(d_sumQ + t * 64 + c0 + 1, sq1);
}

// ---------------- K4: BN stats -> affine scale/shift ----------------
__global__ void k_stats(const float* __restrict__ bng, const float* __restrict__ bnb) {
    int i = threadIdx.x;
    if (i < NTYPE * CH) {
        const float invE = 1.f / (float)EDGES;
        float m = d_sumP[i] * invE;
        float v = fmaf(d_sumQ[i], invE, -m * m);
        float sc = bng[i] * rsqrtf(v + 1e-5f);
        d_scale[i] = sc;
        d_shift[i] = fmaf(-m, sc, bnb[i]);
    }
}

// ---------------- K5: node kernel ----------------
__global__ void __launch_bounds__(128) k_node(const float* __restrict__ feats,
                                              const float* __restrict__ Wr,
                                              const float* __restrict__ br,
                                              float* __restrict__ out) {
    __shared__ float wr[64 * 64];
    __shared__ float sc[NTYPE * CH], sh[NTYPE * CH];
    for (int i = threadIdx.x; i < 64 * 64; i += 128) wr[i] = Wr[i];
    for (int i = threadIdx.x; i < NTYPE * CH; i += 128) {
        sc[i] = d_scale[i];
        sh[i] = d_shift[i];
    }
    __syncthreads();

    int n = blockIdx.x * 128 + threadIdx.x;
    if (n >= NODES) return;

    float u[64];
#pragma unroll
    for (int c = 0; c < 64; c++) u[c] = 0.f;
#pragma unroll
    for (int t = 0; t < NTYPE; t++) {
        const float cf = (float)d_cnt[t * NODES + n];
        const float* Sn = d_S + ((size_t)t * NODES + n) * 64;
#pragma unroll
        for (int j = 0; j < 16; j++) {
            float4 sv = *(const float4*)(Sn + 4 * j);
            u[4 * j + 0] = fmaf(sc[t * 64 + 4 * j + 0], sv.x, fmaf(sh[t * 64 + 4 * j + 0], cf, u[4 * j + 0]));
            u[4 * j + 1] = fmaf(sc[t * 64 + 4 * j + 1], sv.y, fmaf(sh[t * 64 + 4 * j + 1], cf, u[4 * j + 1]));
            u[4 * j + 2] = fmaf(sc[t * 64 + 4 * j + 2], sv.z, fmaf(sh[t * 64 + 4 * j + 2], cf, u[4 * j + 2]));
            u[4 * j + 3] = fmaf(sc[t * 64 + 4 * j + 3], sv.w, fmaf(sh[t * 64 + 4 * j + 3], cf, u[4 * j + 3]));
        }
    }

    const float* fn = feats + (size_t)n * 64;
    float* on = out + (size_t)n * 64;
    for (int o = 0; o < 64; o += 4) {
        float a0 = br[o], a1 = br[o + 1], a2 = br[o + 2], a3 = br[o + 3];
#pragma unroll
        for (int k = 0; k < 64; k++) {
            float4 wv = *(const float4*)(&wr[k * 64 + o]);
            a0 = fmaf(u[k], wv.x, a0);
            a1 = fmaf(u[k], wv.y, a1);
            a2 = fmaf(u[k], wv.z, a2);
            a3 = fmaf(u[k], wv.w, a3);
        }
        float4 fv = *(const float4*)(fn + o);
        float4 r = make_float4(a0 + fv.x, a1 + fv.y, a2 + fv.z, a3 + fv.w);
        *(float4*)(on + o) = r;
    }
}

// ---------------- launch ----------------
extern "C" void kernel_launch(void* const* d_in, const int* in_sizes, int n_in,
                              void* d_out, int out_size) {
    const float* feats = (const float*)d_in[0];
    const float* W1    = (const float*)d_in[1];
    const float* b1    = (const float*)d_in[2];
    const float* lng   = (const float*)d_in[3];
    const float* lnb   = (const float*)d_in[4];
    const float* W2    = (const float*)d_in[5];
    const float* b2    = (const float*)d_in[6];
    const float* bng   = (const float*)d_in[7];
    const float* bnb   = (const float*)d_in[8];
    const float* Wr    = (const float*)d_in[9];
    const float* br    = (const float*)d_in[10];
    const void*  esrc  = d_in[11];
    const void*  edst  = d_in[12];
    float* out = (float*)d_out;

    k_detect<<<1, 32>>>((const int*)esrc);

    {
        long long tot = (long long)NTYPE * EDGES;
        int blocks = (int)((tot + 255) / 256);
        k_convert<<<blocks, 256>>>(esrc, edst);
    }
    {
        long long nS4 = (long long)NTYPE * NODES * CH / 4;
        int blocks = (int)((nS4 + 255) / 256);
        k_zero<<<blocks, 256>>>();
    }
    {
        dim3 g((NODES + 127) / 128, NTYPE);
        k_pre<<<g, 128>>>(feats, W1);
    }
    {
        dim3 g(148, NTYPE);
        k_edge<<<g, 128>>>(W2, b1, lng, lnb, b2);
    }
    k_stats<<<1, 256>>>(bng, bnb);
    {
        int blocks = (NODES + 127) / 128;
        k_node<<<blocks, 128>>>(feats, Wr, br, out);
    }
}

// round 4
// speedup vs baseline: 1.6811x; 1.0734x over previous
#include <cuda_runtime.h>
#include <cuda_bf16.h>

#define NODES 50000
#define EDGES 800000
#define NTYPE 3
#define CH    64

// ---------------- static device scratch (no allocation) ----------------
__device__ float d_A[NTYPE * NODES * CH];    // A[t][n][c] = feat[n] @ W1[t][0:64,:]
__device__ float d_B[NTYPE * NODES * CH];    // B[t][n][c] = feat[n] @ W1[t][64:128,:]
__device__ float d_S[NTYPE * NODES * CH];    // raw p scatter sums per (t,dst,c)
__device__ int   d_cnt[NTYPE * NODES];       // edge counts per (t,dst)
__device__ float d_sumP[NTYPE * CH];         // BN: sum p
__device__ float d_sumQ[NTYPE * CH];         // BN: sum p^2
__device__ float d_scale[NTYPE * CH];        // BN affine (derived)
__device__ float d_shift[NTYPE * CH];
__device__ int   d_src[NTYPE * EDGES];
__device__ int   d_dst[NTYPE * EDGES];
__device__ int   d_is64;

// ---------------- helpers ----------------
static __device__ __forceinline__ unsigned long long pack2(float x, float y) {
    unsigned long long r;
    asm("mov.b64 %0, {%1,%2};" : "=l"(r) : "f"(x), "f"(y));
    return r;
}
static __device__ __forceinline__ float2 unpack2(unsigned long long v) {
    float2 f;
    asm("mov.b64 {%0,%1}, %2;" : "=f"(f.x), "=f"(f.y) : "l"(v));
    return f;
}
static __device__ __forceinline__ void ffma2(unsigned long long& d,
                                             unsigned long long a,
                                             unsigned long long b) {
    asm("fma.rn.f32x2 %0, %1, %2, %0;" : "+l"(d) : "l"(a), "l"(b));
}
static __device__ __forceinline__ void red2(float* addr, float x, float y) {
    asm volatile("red.global.add.v2.f32 [%0], {%1, %2};"
                 :: "l"(addr), "f"(x), "f"(y) : "memory");
}
static __device__ __forceinline__ float elu1(float x) {
    return x > 0.f ? x : (__expf(x) - 1.f);
}

// ---------------- K0: detect int64 vs int32 edge indices ----------------
__global__ void k_detect(const int* __restrict__ raw) {
    if (threadIdx.x == 0) {
        int is64 = 1;
        for (int i = 0; i < 64; i++) {
            if (raw[2 * i + 1] != 0) { is64 = 0; break; }
        }
        d_is64 = is64;
    }
}

// ---------------- K1: normalize edge indices to int32 ----------------
__global__ void k_convert(const void* __restrict__ sraw, const void* __restrict__ draw) {
    long long i = (long long)blockIdx.x * blockDim.x + threadIdx.x;
    if (i >= (long long)NTYPE * EDGES) return;
    if (d_is64) {
        d_src[i] = (int)((const long long*)sraw)[i];
        d_dst[i] = (int)((const long long*)draw)[i];
    } else {
        d_src[i] = ((const int*)sraw)[i];
        d_dst[i] = ((const int*)draw)[i];
    }
}

// ---------------- K1b: zero scratch ----------------
__global__ void k_zero() {
    long long i = (long long)blockIdx.x * blockDim.x + threadIdx.x;
    const long long nS4 = (long long)NTYPE * NODES * CH / 4;   // float4 count
    if (i < nS4) {
        ((float4*)d_S)[i] = make_float4(0.f, 0.f, 0.f, 0.f);
    }
    if (i < NTYPE * NODES) d_cnt[i] = 0;
    if (i < NTYPE * CH) { d_sumP[i] = 0.f; d_sumQ[i] = 0.f; }
}

// ---------------- K2: precompute A/B = features @ W1 halves ----------------
__global__ void __launch_bounds__(128) k_pre(const float* __restrict__ feats,
                                             const float* __restrict__ W1) {
    __shared__ float w1t[128 * 64];  // w1t[o*64+k]
    const int t = blockIdx.y;
    const float* W1t = W1 + t * 128 * 64;
    for (int i = threadIdx.x; i < 128 * 64; i += 128) {
        int o = i >> 6, k = i & 63;
        w1t[i] = W1t[(((o >> 6) << 6) + k) * 64 + (o & 63)];
    }
    __syncthreads();
    int n = blockIdx.x * 128 + threadIdx.x;
    if (n >= NODES) return;

    float f[64];
#pragma unroll
    for (int j = 0; j < 16; j++) {
        float4 v = *(const float4*)(feats + (size_t)n * 64 + 4 * j);
        f[4 * j] = v.x; f[4 * j + 1] = v.y; f[4 * j + 2] = v.z; f[4 * j + 3] = v.w;
    }
    float* outA = d_A + ((size_t)t * NODES + n) * 64;
    float* outB = d_B + ((size_t)t * NODES + n) * 64;

    for (int og = 0; og < 32; og++) {
        float a0 = 0.f, a1 = 0.f, a2 = 0.f, a3 = 0.f;
        const float* wp = &w1t[og * 4 * 64];
#pragma unroll
        for (int k = 0; k < 64; k += 4) {
            float4 v0 = *(const float4*)(wp + 0 * 64 + k);
            float4 v1 = *(const float4*)(wp + 1 * 64 + k);
            float4 v2 = *(const float4*)(wp + 2 * 64 + k);
            float4 v3 = *(const float4*)(wp + 3 * 64 + k);
            a0 = fmaf(v0.x, f[k], a0); a0 = fmaf(v0.y, f[k + 1], a0);
            a0 = fmaf(v0.z, f[k + 2], a0); a0 = fmaf(v0.w, f[k + 3], a0);
            a1 = fmaf(v1.x, f[k], a1); a1 = fmaf(v1.y, f[k + 1], a1);
            a1 = fmaf(v1.z, f[k + 2], a1); a1 = fmaf(v1.w, f[k + 3], a1);
            a2 = fmaf(v2.x, f[k], a2); a2 = fmaf(v2.y, f[k + 1], a2);
            a2 = fmaf(v2.z, f[k + 2], a2); a2 = fmaf(v2.w, f[k + 3], a2);
            a3 = fmaf(v3.x, f[k], a3); a3 = fmaf(v3.y, f[k + 1], a3);
            a3 = fmaf(v3.z, f[k + 2], a3); a3 = fmaf(v3.w, f[k + 3], a3);
        }
        float4 r = make_float4(a0, a1, a2, a3);
        if (og < 16) *(float4*)(outA + og * 4) = r;
        else         *(float4*)(outB + (og - 16) * 4) = r;
    }
}

// ---------------- K3: edge kernel, quad-edge pipelined ----------------
__global__ void __launch_bounds__(128, 2) k_edge(const float* __restrict__ W2,
                                                 const float* __restrict__ b1,
                                                 const float* __restrict__ lng,
                                                 const float* __restrict__ lnb,
                                                 const float* __restrict__ b2) {
    const int t = blockIdx.y;
    const int w = threadIdx.x >> 5;
    const int lane = threadIdx.x & 31;
    const int c0 = lane * 2;

    __shared__ __align__(16) float hdup[4][4][128];  // [warp][edge][dup pairs] = 8KB

    // register-cached W2 column pairs: w2r[k] = (W2[t][k][c0], W2[t][k][c0+1])
    unsigned long long w2r[64];
    const float* W2t = W2 + t * 64 * 64 + c0;
#pragma unroll
    for (int k = 0; k < 64; k++) {
        float2 wv = *(const float2*)(W2t + k * 64);
        w2r[k] = pack2(wv.x, wv.y);
    }
    const float2 b1v = *(const float2*)(b1 + t * 64 + c0);
    const float2 gv  = *(const float2*)(lng + t * 64 + c0);
    const float2 lbv = *(const float2*)(lnb + t * 64 + c0);
    const float2 b2v = *(const float2*)(b2 + t * 64 + c0);
    const unsigned long long accInit = pack2(b2v.x, b2v.y);

    const int*   srcp = d_src + (size_t)t * EDGES;
    const int*   dstp = d_dst + (size_t)t * EDGES;
    const float* At   = d_A + (size_t)t * NODES * 64;
    const float* Bt   = d_B + (size_t)t * NODES * 64;
    float*       St   = d_S + (size_t)t * NODES * 64;
    int*         cntp = d_cnt + (size_t)t * NODES;

    float sp0 = 0.f, sp1 = 0.f, sq0 = 0.f, sq1 = 0.f;

    const int nquads  = EDGES / 4;           // 200000, exact
    const int qstride = gridDim.x * 4;
    int q = blockIdx.x * 4 + w;

    if (q < nquads) {
        int dst[4];
        float2 av[4], bv[4];
        {
            const int e = q * 4;
#pragma unroll
            for (int i = 0; i < 4; i++) {
                const int s = srcp[e + i];
                dst[i] = dstp[e + i];
                av[i] = *(const float2*)(At + (size_t)s * 64 + c0);
                bv[i] = *(const float2*)(Bt + (size_t)dst[i] * 64 + c0);
            }
        }

        while (true) {
            const int qn = q + qstride;
            const bool more = (qn < nquads);

            // --- ELU + LayerNorm for 4 edges (interleaved butterfly chains) ---
            float h0[4], h1[4], s[4], qq[4];
#pragma unroll
            for (int i = 0; i < 4; i++) {
                h0[i] = elu1(av[i].x + bv[i].x + b1v.x);
                h1[i] = elu1(av[i].y + bv[i].y + b1v.y);
                s[i]  = h0[i] + h1[i];
                qq[i] = fmaf(h0[i], h0[i], h1[i] * h1[i]);
            }
#pragma unroll
            for (int off = 16; off; off >>= 1) {
#pragma unroll
                for (int i = 0; i < 4; i++) {
                    s[i]  += __shfl_xor_sync(0xffffffffu, s[i], off);
                    qq[i] += __shfl_xor_sync(0xffffffffu, qq[i], off);
                }
            }
#pragma unroll
            for (int i = 0; i < 4; i++) {
                const float mu = s[i] * (1.f / 64.f);
                const float rs = rsqrtf(fmaf(qq[i], (1.f / 64.f), -mu * mu) + 1e-5f);
                const float hn0 = fmaf((h0[i] - mu) * rs, gv.x, lbv.x);
                const float hn1 = fmaf((h1[i] - mu) * rs, gv.y, lbv.y);
                *(float4*)(&hdup[w][i][4 * lane]) = make_float4(hn0, hn0, hn1, hn1);
            }
            __syncwarp();

            // --- prefetch next quad under the GEMM ---
            int dstc0 = dst[0], dstc1 = dst[1], dstc2 = dst[2], dstc3 = dst[3];
            float2 avn[4], bvn[4];
            int dstn[4];
#pragma unroll
            for (int i = 0; i < 4; i++) {
                avn[i] = make_float2(0.f, 0.f);
                bvn[i] = make_float2(0.f, 0.f);
                dstn[i] = 0;
            }
            if (more) {
                const int en = qn * 4;
#pragma unroll
                for (int i = 0; i < 4; i++) {
                    const int sn = srcp[en + i];
                    dstn[i] = dstp[en + i];
                    avn[i] = *(const float2*)(At + (size_t)sn * 64 + c0);
                    bvn[i] = *(const float2*)(Bt + (size_t)dstn[i] * 64 + c0);
                }
            }

            // --- GEMM2 for 4 edges, 8 independent FMA chains ---
            unsigned long long accA[4], accB[4];
#pragma unroll
            for (int i = 0; i < 4; i++) { accA[i] = accInit; accB[i] = 0ULL; }
            const ulonglong2* hp0 = (const ulonglong2*)&hdup[w][0][0];
            const ulonglong2* hp1 = (const ulonglong2*)&hdup[w][1][0];
            const ulonglong2* hp2 = (const ulonglong2*)&hdup[w][2][0];
            const ulonglong2* hp3 = (const ulonglong2*)&hdup[w][3][0];
#pragma unroll
            for (int kk = 0; kk < 32; kk++) {
                const unsigned long long wA = w2r[2 * kk];
                const unsigned long long wB = w2r[2 * kk + 1];
                ulonglong2 g0 = hp0[kk];
                ulonglong2 g1 = hp1[kk];
                ulonglong2 g2 = hp2[kk];
                ulonglong2 g3 = hp3[kk];
                ffma2(accA[0], g0.x, wA); ffma2(accB[0], g0.y, wB);
                ffma2(accA[1], g1.x, wA); ffma2(accB[1], g1.y, wB);
                ffma2(accA[2], g2.x, wA); ffma2(accB[2], g2.y, wB);
                ffma2(accA[3], g3.x, wA); ffma2(accB[3], g3.y, wB);
            }

            float p0[4], p1[4];
#pragma unroll
            for (int i = 0; i < 4; i++) {
                float2 ra = unpack2(accA[i]);
                float2 rb = unpack2(accB[i]);
                p0[i] = elu1(ra.x + rb.x);
                p1[i] = elu1(ra.y + rb.y);
            }

            // BN running sums
#pragma unroll
            for (int i = 0; i < 4; i++) {
                sp0 += p0[i];
                sp1 += p1[i];
                sq0 = fmaf(p0[i], p0[i], sq0);
                sq1 = fmaf(p1[i], p1[i], sq1);
            }

            // scatter raw p
            red2(St + (size_t)dstc0 * 64 + c0, p0[0], p1[0]);
            red2(St + (size_t)dstc1 * 64 + c0, p0[1], p1[1]);
            red2(St + (size_t)dstc2 * 64 + c0, p0[2], p1[2]);
            red2(St + (size_t)dstc3 * 64 + c0, p0[3], p1[3]);
            {
                int mydst = dstc0;
                if (lane == 1) mydst = dstc1;
                else if (lane == 2) mydst = dstc2;
                else if (lane == 3) mydst = dstc3;
                if (lane < 4) atomicAdd(cntp + mydst, 1);
            }

            __syncwarp();
            if (!more) break;
            q = qn;
#pragma unroll
            for (int i = 0; i < 4; i++) {
                dst[i] = dstn[i];
                av[i] = avn[i];
                bv[i] = bvn[i];
            }
        }
    }
    // flush BN partial sums
    atomicAdd(d_sumP + t * 64 + c0,     sp0);
    atomicAdd(d_sumP + t * 64 + c0 + 1, sp1);
    atomicAdd(d_sumQ + t * 64 + c0,     sq0);
    atomicAdd(d_sumQ + t * 64 + c0 + 1, sq1);
}

// ---------------- K4: BN stats -> affine scale/shift ----------------
__global__ void k_stats(const float* __restrict__ bng, const float* __restrict__ bnb) {
    int i = threadIdx.x;
    if (i < NTYPE * CH) {
        const float invE = 1.f / (float)EDGES;
        float m = d_sumP[i] * invE;
        float v = fmaf(d_sumQ[i], invE, -m * m);
        float sc = bng[i] * rsqrtf(v + 1e-5f);
        d_scale[i] = sc;
        d_shift[i] = fmaf(-m, sc, bnb[i]);
    }
}

// ---------------- K5: node kernel ----------------
__global__ void __launch_bounds__(128) k_node(const float* __restrict__ feats,
                                              const float* __restrict__ Wr,
                                              const float* __restrict__ br,
                                              float* __restrict__ out) {
    __shared__ float wr[64 * 64];
    __shared__ float sc[NTYPE * CH], sh[NTYPE * CH];
    for (int i = threadIdx.x; i < 64 * 64; i += 128) wr[i] = Wr[i];
    for (int i = threadIdx.x; i < NTYPE * CH; i += 128) {
        sc[i] = d_scale[i];
        sh[i] = d_shift[i];
    }
    __syncthreads();

    int n = blockIdx.x * 128 + threadIdx.x;
    if (n >= NODES) return;

    float u[64];
#pragma unroll
    for (int c = 0; c < 64; c++) u[c] = 0.f;
#pragma unroll
    for (int t = 0; t < NTYPE; t++) {
        const float cf = (float)d_cnt[t * NODES + n];
        const float* Sn = d_S + ((size_t)t * NODES + n) * 64;
#pragma unroll
        for (int j = 0; j < 16; j++) {
            float4 sv = *(const float4*)(Sn + 4 * j);
            u[4 * j + 0] = fmaf(sc[t * 64 + 4 * j + 0], sv.x, fmaf(sh[t * 64 + 4 * j + 0], cf, u[4 * j + 0]));
            u[4 * j + 1] = fmaf(sc[t * 64 + 4 * j + 1], sv.y, fmaf(sh[t * 64 + 4 * j + 1], cf, u[4 * j + 1]));
            u[4 * j + 2] = fmaf(sc[t * 64 + 4 * j + 2], sv.z, fmaf(sh[t * 64 + 4 * j + 2], cf, u[4 * j + 2]));
            u[4 * j + 3] = fmaf(sc[t * 64 + 4 * j + 3], sv.w, fmaf(sh[t * 64 + 4 * j + 3], cf, u[4 * j + 3]));
        }
    }

    const float* fn = feats + (size_t)n * 64;
    float* on = out + (size_t)n * 64;
    for (int o = 0; o < 64; o += 4) {
        float a0 = br[o], a1 = br[o + 1], a2 = br[o + 2], a3 = br[o + 3];
#pragma unroll
        for (int k = 0; k < 64; k++) {
            float4 wv = *(const float4*)(&wr[k * 64 + o]);
            a0 = fmaf(u[k], wv.x, a0);
            a1 = fmaf(u[k], wv.y, a1);
            a2 = fmaf(u[k], wv.z, a2);
            a3 = fmaf(u[k], wv.w, a3);
        }
        float4 fv = *(const float4*)(fn + o);
        float4 r = make_float4(a0 + fv.x, a1 + fv.y, a2 + fv.z, a3 + fv.w);
        *(float4*)(on + o) = r;
    }
}

// ---------------- launch ----------------
extern "C" void kernel_launch(void* const* d_in, const int* in_sizes, int n_in,
                              void* d_out, int out_size) {
    const float* feats = (const float*)d_in[0];
    const float* W1    = (const float*)d_in[1];
    const float* b1    = (const float*)d_in[2];
    const float* lng   = (const float*)d_in[3];
    const float* lnb   = (const float*)d_in[4];
    const float* W2    = (const float*)d_in[5];
    const float* b2    = (const float*)d_in[6];
    const float* bng   = (const float*)d_in[7];
    const float* bnb   = (const float*)d_in[8];
    const float* Wr    = (const float*)d_in[9];
    const float* br    = (const float*)d_in[10];
    const void*  esrc  = d_in[11];
    const void*  edst  = d_in[12];
    float* out = (float*)d_out;

    k_detect<<<1, 32>>>((const int*)esrc);

    {
        long long tot = (long long)NTYPE * EDGES;
        int blocks = (int)((tot + 255) / 256);
        k_convert<<<blocks, 256>>>(esrc, edst);
    }
    {
        long long nS4 = (long long)NTYPE * NODES * CH / 4;
        int blocks = (int)((nS4 + 255) / 256);
        k_zero<<<blocks, 256>>>();
    }
    {
        dim3 g((NODES + 127) / 128, NTYPE);
        k_pre<<<g, 128>>>(feats, W1);
    }
    {
        dim3 g(98, NTYPE);   // 294 blocks = one resident wave at 2 blocks/SM
        k_edge<<<g, 128>>>(W2, b1, lng, lnb, b2);
    }
    k_stats<<<1, 256>>>(bng, bnb);
    {
        int blocks = (NODES + 127) / 128;
        k_node<<<blocks, 128>>>(feats, Wr, br, out);
    }
}